// round 2
// baseline (speedup 1.0000x reference)
#include <cuda_runtime.h>
#include <cstdint>

#define NN 100000       // nodes
#define NE 1600000      // edges
#define NG 512          // graphs
#define DIN 128
#define DHID 256
#define DOUT 128

// Scratch as float4 arrays => guaranteed 16B alignment (allocation-free rule)
__device__ float4 g_agg4[NN * DIN  / 4];   //  51.2 MB
__device__ float4 g_h1_4[NN * DHID / 4];   // 102.4 MB
__device__ float4 g_h2_4[NN * DHID / 4];   // 102.4 MB

// ---------------------------------------------------------------------------
// Kernel 1: agg = x   (GIN with eps=0: h = x + sum_neighbors)
// ---------------------------------------------------------------------------
__global__ void init_agg_kernel(const float4* __restrict__ x4) {
    int i = blockIdx.x * blockDim.x + threadIdx.x;
    const int n4 = NN * DIN / 4;
    if (i < n4) g_agg4[i] = x4[i];
}

// ---------------------------------------------------------------------------
// Kernel 2: scatter-add  agg[dst] += x[src]   (one warp per edge, red.v4)
// ---------------------------------------------------------------------------
__device__ __forceinline__ void red_add_v4(float* p, float a, float b, float c, float d) {
    asm volatile("red.global.add.v4.f32 [%0], {%1,%2,%3,%4};"
                 :: "l"(p), "f"(a), "f"(b), "f"(c), "f"(d) : "memory");
}

__global__ void scatter_kernel(const float* __restrict__ x,
                               const int* __restrict__ ei) {
    unsigned e    = (blockIdx.x * blockDim.x + threadIdx.x) >> 5;
    unsigned lane = threadIdx.x & 31;
    if (e >= NE) return;
    int src = ei[e];        // all lanes read the same 4B -> L1 broadcast
    int dst = ei[NE + e];
    const float4 v = *reinterpret_cast<const float4*>(x + (size_t)src * DIN + lane * 4);
    float* p = reinterpret_cast<float*>(g_agg4) + (size_t)dst * DIN + lane * 4;
    red_add_v4(p, v.x, v.y, v.z, v.w);
}

// ---------------------------------------------------------------------------
// Tiled fp32 GEMM:  C[M,N] = act(A[M,K] @ W[K,N] + bias)
// BM=128, BN=64, BK=16, 256 threads, 8x4 per-thread tile, k-major smem.
// ---------------------------------------------------------------------------
#define BM 128
#define BN 64
#define BK 16

template<bool RELU>
__global__ void __launch_bounds__(256)
gemm_kernel(const float* __restrict__ A, const float* __restrict__ W,
            const float* __restrict__ bias, float* __restrict__ C,
            int M, int N, int K)
{
    __shared__ float As[BK][BM];
    __shared__ float Bs[BK][BN];

    const int tid  = threadIdx.x;
    const int row0 = blockIdx.x * BM;
    const int col0 = blockIdx.y * BN;
    const int tr   = (tid >> 4) * 8;   // thread row within tile (0,8,...,120)
    const int tc   = (tid & 15) * 4;   // thread col within tile (0,4,...,60)

    float acc[8][4];
    #pragma unroll
    for (int i = 0; i < 8; i++)
        #pragma unroll
        for (int j = 0; j < 4; j++) acc[i][j] = 0.f;

    for (int k0 = 0; k0 < K; k0 += BK) {
        // A tile 128x16 -> As[k][row]  (8 elems/thread)
        #pragma unroll
        for (int l = 0; l < 8; l++) {
            int lin = tid + l * 256;
            int r   = lin >> 4;
            int kk  = lin & 15;
            int gr  = row0 + r;
            As[kk][r] = (gr < M) ? A[(size_t)gr * K + k0 + kk] : 0.f;
        }
        // W tile 16x64 -> Bs[k][col]  (4 elems/thread, coalesced along n)
        #pragma unroll
        for (int l = 0; l < 4; l++) {
            int lin = tid + l * 256;
            int r   = lin >> 6;
            int c   = lin & 63;
            Bs[r][c] = W[(size_t)(k0 + r) * N + col0 + c];
        }
        __syncthreads();
        #pragma unroll
        for (int kk = 0; kk < BK; kk++) {
            float a[8], b[4];
            #pragma unroll
            for (int i = 0; i < 8; i++) a[i] = As[kk][tr + i];
            #pragma unroll
            for (int j = 0; j < 4; j++) b[j] = Bs[kk][tc + j];
            #pragma unroll
            for (int i = 0; i < 8; i++)
                #pragma unroll
                for (int j = 0; j < 4; j++)
                    acc[i][j] += a[i] * b[j];
        }
        __syncthreads();
    }

    const int cbase = col0 + tc;
    float b0 = bias[cbase], b1 = bias[cbase+1], b2 = bias[cbase+2], b3 = bias[cbase+3];
    #pragma unroll
    for (int i = 0; i < 8; i++) {
        int gr = row0 + tr + i;
        if (gr < M) {
            float4 o;
            o.x = acc[i][0] + b0; o.y = acc[i][1] + b1;
            o.z = acc[i][2] + b2; o.w = acc[i][3] + b3;
            if (RELU) {
                o.x = fmaxf(o.x, 0.f); o.y = fmaxf(o.y, 0.f);
                o.z = fmaxf(o.z, 0.f); o.w = fmaxf(o.w, 0.f);
            }
            *reinterpret_cast<float4*>(&C[(size_t)gr * N + cbase]) = o;
        }
    }
}

// ---------------------------------------------------------------------------
// GEMM3 + global_add_pool fused epilogue.
// batch_ids sorted -> run-length-compress per thread's 8 consecutive rows
// before the atomic, then red.v4 into pooled[graph].
// ---------------------------------------------------------------------------
__global__ void __launch_bounds__(256)
gemm_pool_kernel(const float* __restrict__ A, const float* __restrict__ W,
                 const float* __restrict__ bias,
                 const int* __restrict__ batch_ids,
                 float* __restrict__ pooled,
                 int M, int N, int K)
{
    __shared__ float As[BK][BM];
    __shared__ float Bs[BK][BN];

    const int tid  = threadIdx.x;
    const int row0 = blockIdx.x * BM;
    const int col0 = blockIdx.y * BN;
    const int tr   = (tid >> 4) * 8;
    const int tc   = (tid & 15) * 4;

    float acc[8][4];
    #pragma unroll
    for (int i = 0; i < 8; i++)
        #pragma unroll
        for (int j = 0; j < 4; j++) acc[i][j] = 0.f;

    for (int k0 = 0; k0 < K; k0 += BK) {
        #pragma unroll
        for (int l = 0; l < 8; l++) {
            int lin = tid + l * 256;
            int r   = lin >> 4;
            int kk  = lin & 15;
            int gr  = row0 + r;
            As[kk][r] = (gr < M) ? A[(size_t)gr * K + k0 + kk] : 0.f;
        }
        #pragma unroll
        for (int l = 0; l < 4; l++) {
            int lin = tid + l * 256;
            int r   = lin >> 6;
            int c   = lin & 63;
            Bs[r][c] = W[(size_t)(k0 + r) * N + col0 + c];
        }
        __syncthreads();
        #pragma unroll
        for (int kk = 0; kk < BK; kk++) {
            float a[8], b[4];
            #pragma unroll
            for (int i = 0; i < 8; i++) a[i] = As[kk][tr + i];
            #pragma unroll
            for (int j = 0; j < 4; j++) b[j] = Bs[kk][tc + j];
            #pragma unroll
            for (int i = 0; i < 8; i++)
                #pragma unroll
                for (int j = 0; j < 4; j++)
                    acc[i][j] += a[i] * b[j];
        }
        __syncthreads();
    }

    const int cbase = col0 + tc;
    const float b0 = bias[cbase], b1 = bias[cbase+1],
                b2 = bias[cbase+2], b3 = bias[cbase+3];

    int cur = -1;
    float s0 = 0.f, s1 = 0.f, s2 = 0.f, s3 = 0.f;
    #pragma unroll
    for (int i = 0; i < 8; i++) {
        int gr = row0 + tr + i;
        if (gr < M) {
            int g = batch_ids[gr];
            if (g != cur) {
                if (cur >= 0)
                    red_add_v4(&pooled[(size_t)cur * N + cbase], s0, s1, s2, s3);
                cur = g; s0 = s1 = s2 = s3 = 0.f;
            }
            s0 += acc[i][0] + b0;
            s1 += acc[i][1] + b1;
            s2 += acc[i][2] + b2;
            s3 += acc[i][3] + b3;
        }
    }
    if (cur >= 0)
        red_add_v4(&pooled[(size_t)cur * N + cbase], s0, s1, s2, s3);
}

// ---------------------------------------------------------------------------
// Launch
// ---------------------------------------------------------------------------
extern "C" void kernel_launch(void* const* d_in, const int* in_sizes, int n_in,
                              void* d_out, int out_size)
{
    const float* x   = (const float*)d_in[0];
    const int*   ei  = (const int*)d_in[1];    // int32 (JAX x64 disabled)
    const int*   bid = (const int*)d_in[2];
    const float* W1  = (const float*)d_in[3];
    const float* b1  = (const float*)d_in[4];
    const float* W2  = (const float*)d_in[5];
    const float* b2  = (const float*)d_in[6];
    const float* Wo  = (const float*)d_in[7];
    const float* bo  = (const float*)d_in[8];
    float*       out = (float*)d_out;

    float *agg, *h1, *h2;
    cudaGetSymbolAddress((void**)&agg, g_agg4);
    cudaGetSymbolAddress((void**)&h1,  g_h1_4);
    cudaGetSymbolAddress((void**)&h2,  g_h2_4);

    // 1) agg = x
    {
        int n4 = NN * DIN / 4;
        init_agg_kernel<<<(n4 + 255) / 256, 256>>>((const float4*)x);
    }
    // 2) agg[dst] += x[src]   (one warp/edge)
    {
        long long threads = (long long)NE * 32;
        int blocks = (int)((threads + 255) / 256);   // 200000
        scatter_kernel<<<blocks, 256>>>(x, ei);
    }
    // 3) h1 = relu(agg @ W1 + b1)    [100000 x 256], K=128
    {
        dim3 grid((NN + BM - 1) / BM, DHID / BN);
        gemm_kernel<true><<<grid, 256>>>(agg, W1, b1, h1, NN, DHID, DIN);
    }
    // 4) h2 = relu(h1 @ W2 + b2)     [100000 x 256], K=256
    {
        dim3 grid((NN + BM - 1) / BM, DHID / BN);
        gemm_kernel<true><<<grid, 256>>>(h1, W2, b2, h2, NN, DHID, DHID);
    }
    // 5) pooled = segment_sum(h2 @ Wo + bo, batch_ids)
    cudaMemsetAsync(d_out, 0, (size_t)out_size * sizeof(float));
    {
        dim3 grid((NN + BM - 1) / BM, DOUT / BN);
        gemm_pool_kernel<<<grid, 256>>>(h2, Wo, bo, bid, out, NN, DOUT, DHID);
    }
}

// round 5
// speedup vs baseline: 2.1900x; 2.1900x over previous
#include <cuda_runtime.h>
#include <cuda_bf16.h>
#include <cstdint>

#define NN 100000
#define NE 1600000
#define NG 512
#define DIN 128
#define DHID 256
#define DOUT 128

// ---------------- scratch (device globals; allocation-free rule) -----------
__device__ float4 g_agg4[NN * DIN  / 4];   //  51.2 MB
__device__ float4 g_h1_4[NN * DHID / 4];   // 102.4 MB
__device__ float4 g_h2_4[NN * DHID / 4];   // 102.4 MB

// bf16 hi/lo weight planes, layout B[n][k]  (K-major = mma ".col" operand)
__device__ __nv_bfloat16 g_B1h[DHID * DIN ], g_B1l[DHID * DIN ];
__device__ __nv_bfloat16 g_B2h[DHID * DHID], g_B2l[DHID * DHID];
__device__ __nv_bfloat16 g_Boh[DOUT * DHID], g_Bol[DOUT * DHID];

// ---------------- helpers ---------------------------------------------------
__device__ __forceinline__ uint32_t smem_u32(const void* p) {
    uint32_t a;
    asm("{ .reg .u64 t; cvta.to.shared.u64 t, %1; cvt.u32.u64 %0, t; }" : "=r"(a) : "l"(p));
    return a;
}
__device__ __forceinline__ void red_add_v4(float* p, float a, float b, float c, float d) {
    asm volatile("red.global.add.v4.f32 [%0], {%1,%2,%3,%4};"
                 :: "l"(p), "f"(a), "f"(b), "f"(c), "f"(d) : "memory");
}
__device__ __forceinline__ void red_add_v2(float* p, float a, float b) {
    asm volatile("red.global.add.v2.f32 [%0], {%1,%2};"
                 :: "l"(p), "f"(a), "f"(b) : "memory");
}
#define LDSM4(r, a) \
    asm volatile("ldmatrix.sync.aligned.m8n8.x4.shared.b16 {%0,%1,%2,%3}, [%4];" \
        : "=r"((r)[0]), "=r"((r)[1]), "=r"((r)[2]), "=r"((r)[3]) : "r"(a))

__device__ __forceinline__ void mma_bf16(float* d, const uint32_t* a, const uint32_t* b) {
    asm volatile("mma.sync.aligned.m16n8k16.row.col.f32.bf16.bf16.f32 "
        "{%0,%1,%2,%3}, {%4,%5,%6,%7}, {%8,%9}, {%0,%1,%2,%3};"
        : "+f"(d[0]), "+f"(d[1]), "+f"(d[2]), "+f"(d[3])
        : "r"(a[0]), "r"(a[1]), "r"(a[2]), "r"(a[3]), "r"(b[0]), "r"(b[1]));
}

// ---------------- kernel 1: agg = x ---------------------------------------
__global__ void init_agg_kernel(const float4* __restrict__ x4) {
    int i = blockIdx.x * blockDim.x + threadIdx.x;
    if (i < NN * DIN / 4) g_agg4[i] = x4[i];
}

// ---------------- kernel 2: agg[dst] += x[src] ----------------------------
__global__ void scatter_kernel(const float* __restrict__ x, const int* __restrict__ ei) {
    unsigned e = (blockIdx.x * blockDim.x + threadIdx.x) >> 5;
    unsigned lane = threadIdx.x & 31;
    if (e >= NE) return;
    int src = ei[e];
    int dst = ei[NE + e];
    const float4 v = *reinterpret_cast<const float4*>(x + (size_t)src * DIN + lane * 4);
    float* p = reinterpret_cast<float*>(g_agg4) + (size_t)dst * DIN + lane * 4;
    red_add_v4(p, v.x, v.y, v.z, v.w);
}

// ---------------- weight prep: W[K][N] -> Bh/Bl [N][K] bf16 ----------------
__global__ void prep_w_kernel(const float* __restrict__ W,
                              __nv_bfloat16* __restrict__ Bh,
                              __nv_bfloat16* __restrict__ Bl, int K, int N) {
    int idx = blockIdx.x * blockDim.x + threadIdx.x;
    if (idx >= K * N) return;
    int k = idx / N, n = idx % N;
    float v = W[idx];
    __nv_bfloat16 h = __float2bfloat16(v);
    __nv_bfloat16 l = __float2bfloat16(v - __bfloat162float(h));
    Bh[(size_t)n * K + k] = h;
    Bl[(size_t)n * K + k] = l;
}

// ---------------- mma.sync GEMM: C = act(A @ W + b), optional fused pool ---
// 256 threads = 8 warps (4 x 2).  Block tile M=128, N=128, K chunk 32.
// Warp tile m32 x n64.  Split-bf16: 3 MMAs per (hi,lo) operand pair.
template<int K, int N, bool RELU, bool POOL>
__global__ void __launch_bounds__(256)
gin_gemm(const float* __restrict__ A,
         const __nv_bfloat16* __restrict__ Bh_g,
         const __nv_bfloat16* __restrict__ Bl_g,
         const float* __restrict__ bias, float* __restrict__ C,
         const int* __restrict__ batch_ids, int M)
{
    constexpr int KC    = K / 32;
    constexpr int PITCH = 80;                 // 64B data + 16B pad (conflict-free LDSM)
    constexpr int PLANE = 128 * PITCH;        // 10240 B
    constexpr int A_HI = 0, A_LO = PLANE, B_HI = 2 * PLANE, B_LO = 3 * PLANE;

    __shared__ __align__(16) char smem[4 * PLANE];   // 40 KB
    const uint32_t sb = smem_u32(smem);

    const int tid  = threadIdx.x;
    const int wid  = tid >> 5, lane = tid & 31;
    const int wm   = wid & 3, wn = wid >> 2;          // warp grid 4 x 2
    const int g    = lane >> 2, tig = lane & 3;
    const int row0 = blockIdx.x * 128;
    const int ncol0 = blockIdx.y * 128;               // global n offset of block

    // staging roles: thread t -> row t>>1, k-half t&1 (16 elems = 32B bf16)
    const int srow = tid >> 1, shalf = tid & 1;
    const int gr_l = row0 + srow;

    // ldmatrix lane base offsets (hi plane, kk=0)
    uint32_t aoff[2], boff[4];
    {
        int ar = (lane & 7) + ((lane >> 3) & 1) * 8;
        int ak = ((lane >> 4) & 1) * 16;
        #pragma unroll
        for (int mi = 0; mi < 2; mi++)
            aoff[mi] = sb + A_HI + (uint32_t)((wm * 32 + mi * 16 + ar) * PITCH + ak);
        int br = (lane & 7) + ((lane >> 4) & 1) * 8;
        int bk = ((lane >> 3) & 1) * 16;
        #pragma unroll
        for (int ni2 = 0; ni2 < 4; ni2++)
            boff[ni2] = sb + B_HI + (uint32_t)((wn * 64 + ni2 * 16 + br) * PITCH + bk);
    }

    float acc[2][8][4];
    #pragma unroll
    for (int mi = 0; mi < 2; mi++)
        #pragma unroll
        for (int ni = 0; ni < 8; ni++)
            #pragma unroll
            for (int q = 0; q < 4; q++) acc[mi][ni][q] = 0.f;

    for (int kc = 0; kc < KC; kc++) {
        // ---- stage A: fp32 -> bf16 hi/lo ----
        {
            float fl[16];
            if (gr_l < M) {
                const float4* ap = reinterpret_cast<const float4*>(
                    A + (size_t)gr_l * K + kc * 32 + shalf * 16);
                #pragma unroll
                for (int j = 0; j < 4; j++) {
                    float4 v = ap[j];
                    fl[4*j] = v.x; fl[4*j+1] = v.y; fl[4*j+2] = v.z; fl[4*j+3] = v.w;
                }
            } else {
                #pragma unroll
                for (int j = 0; j < 16; j++) fl[j] = 0.f;
            }
            uint32_t hw[8], lw[8];
            #pragma unroll
            for (int i = 0; i < 8; i++) {
                float a = fl[2*i], b = fl[2*i+1];
                __nv_bfloat16 ha = __float2bfloat16(a), hb = __float2bfloat16(b);
                __nv_bfloat16 la = __float2bfloat16(a - __bfloat162float(ha));
                __nv_bfloat16 lb = __float2bfloat16(b - __bfloat162float(hb));
                __nv_bfloat162 hp = __halves2bfloat162(ha, hb);
                __nv_bfloat162 lp = __halves2bfloat162(la, lb);
                hw[i] = *reinterpret_cast<uint32_t*>(&hp);
                lw[i] = *reinterpret_cast<uint32_t*>(&lp);
            }
            char* dsthi = smem + A_HI + srow * PITCH + shalf * 32;
            char* dstlo = smem + A_LO + srow * PITCH + shalf * 32;
            *reinterpret_cast<uint4*>(dsthi)      = make_uint4(hw[0], hw[1], hw[2], hw[3]);
            *reinterpret_cast<uint4*>(dsthi + 16) = make_uint4(hw[4], hw[5], hw[6], hw[7]);
            *reinterpret_cast<uint4*>(dstlo)      = make_uint4(lw[0], lw[1], lw[2], lw[3]);
            *reinterpret_cast<uint4*>(dstlo + 16) = make_uint4(lw[4], lw[5], lw[6], lw[7]);
        }
        // ---- stage B (already bf16, plain copy) ----
        {
            int n = ncol0 + srow;
            const uint4* bh = reinterpret_cast<const uint4*>(
                Bh_g + (size_t)n * K + kc * 32 + shalf * 16);
            const uint4* bl = reinterpret_cast<const uint4*>(
                Bl_g + (size_t)n * K + kc * 32 + shalf * 16);
            char* dsthi = smem + B_HI + srow * PITCH + shalf * 32;
            char* dstlo = smem + B_LO + srow * PITCH + shalf * 32;
            *reinterpret_cast<uint4*>(dsthi)      = bh[0];
            *reinterpret_cast<uint4*>(dsthi + 16) = bh[1];
            *reinterpret_cast<uint4*>(dstlo)      = bl[0];
            *reinterpret_cast<uint4*>(dstlo + 16) = bl[1];
        }
        __syncthreads();

        // ---- compute: 2 k16 steps per chunk ----
        #pragma unroll
        for (int kk = 0; kk < 2; kk++) {
            uint32_t ah[2][4], al[2][4];
            #pragma unroll
            for (int mi = 0; mi < 2; mi++) {
                LDSM4(ah[mi], aoff[mi] + kk * 32);
                LDSM4(al[mi], aoff[mi] + kk * 32 + PLANE);
            }
            #pragma unroll
            for (int ni2 = 0; ni2 < 4; ni2++) {
                uint32_t bh[4], bl[4];
                LDSM4(bh, boff[ni2] + kk * 32);
                LDSM4(bl, boff[ni2] + kk * 32 + PLANE);
                #pragma unroll
                for (int mi = 0; mi < 2; mi++) {
                    mma_bf16(acc[mi][2*ni2],   ah[mi], bh);
                    mma_bf16(acc[mi][2*ni2],   ah[mi], bl);
                    mma_bf16(acc[mi][2*ni2],   al[mi], bh);
                    mma_bf16(acc[mi][2*ni2+1], ah[mi], bh + 2);
                    mma_bf16(acc[mi][2*ni2+1], ah[mi], bl + 2);
                    mma_bf16(acc[mi][2*ni2+1], al[mi], bh + 2);
                }
            }
        }
        __syncthreads();
    }

    // ---- epilogue ----
    if (!POOL) {
        #pragma unroll
        for (int mi = 0; mi < 2; mi++) {
            int r0 = row0 + wm * 32 + mi * 16 + g;
            #pragma unroll
            for (int ni = 0; ni < 8; ni++) {
                int cg = ncol0 + wn * 64 + ni * 8 + tig * 2;
                float bx = bias[cg], by = bias[cg + 1];
                if (r0 < M) {
                    float2 o;
                    o.x = acc[mi][ni][0] + bx;
                    o.y = acc[mi][ni][1] + by;
                    if (RELU) { o.x = fmaxf(o.x, 0.f); o.y = fmaxf(o.y, 0.f); }
                    *reinterpret_cast<float2*>(&C[(size_t)r0 * N + cg]) = o;
                }
                if (r0 + 8 < M) {
                    float2 o;
                    o.x = acc[mi][ni][2] + bx;
                    o.y = acc[mi][ni][3] + by;
                    if (RELU) { o.x = fmaxf(o.x, 0.f); o.y = fmaxf(o.y, 0.f); }
                    *reinterpret_cast<float2*>(&C[(size_t)(r0 + 8) * N + cg]) = o;
                }
            }
        }
    } else {
        // rows this thread owns (ascending): base+g, +8, +16, +24
        int base = row0 + wm * 32 + g;
        int rows[4] = { base, base + 8, base + 16, base + 24 };
        int bids[4];
        #pragma unroll
        for (int e = 0; e < 4; e++)
            bids[e] = (rows[e] < M) ? batch_ids[rows[e]] : -1;

        #pragma unroll
        for (int ni = 0; ni < 8; ni++) {
            int cg = ncol0 + wn * 64 + ni * 8 + tig * 2;
            float bx = bias[cg], by = bias[cg + 1];
            float v0[4], v1[4];
            v0[0] = acc[0][ni][0] + bx; v1[0] = acc[0][ni][1] + by;
            v0[1] = acc[0][ni][2] + bx; v1[1] = acc[0][ni][3] + by;
            v0[2] = acc[1][ni][0] + bx; v1[2] = acc[1][ni][1] + by;
            v0[3] = acc[1][ni][2] + bx; v1[3] = acc[1][ni][3] + by;
            int cur = -1; float s0 = 0.f, s1 = 0.f;
            #pragma unroll
            for (int e = 0; e < 4; e++) {
                if (bids[e] < 0) continue;
                if (bids[e] != cur) {
                    if (cur >= 0) red_add_v2(&C[(size_t)cur * N + cg], s0, s1);
                    cur = bids[e]; s0 = 0.f; s1 = 0.f;
                }
                s0 += v0[e]; s1 += v1[e];
            }
            if (cur >= 0) red_add_v2(&C[(size_t)cur * N + cg], s0, s1);
        }
    }
}

// ---------------- launch ---------------------------------------------------
extern "C" void kernel_launch(void* const* d_in, const int* in_sizes, int n_in,
                              void* d_out, int out_size)
{
    const float* x   = (const float*)d_in[0];
    const int*   ei  = (const int*)d_in[1];
    const int*   bid = (const int*)d_in[2];
    const float* W1  = (const float*)d_in[3];
    const float* b1  = (const float*)d_in[4];
    const float* W2  = (const float*)d_in[5];
    const float* b2  = (const float*)d_in[6];
    const float* Wo  = (const float*)d_in[7];
    const float* bo  = (const float*)d_in[8];
    float*       out = (float*)d_out;

    float *agg, *h1, *h2;
    cudaGetSymbolAddress((void**)&agg, g_agg4);
    cudaGetSymbolAddress((void**)&h1,  g_h1_4);
    cudaGetSymbolAddress((void**)&h2,  g_h2_4);
    __nv_bfloat16 *B1h, *B1l, *B2h, *B2l, *Boh, *Bol;
    cudaGetSymbolAddress((void**)&B1h, g_B1h); cudaGetSymbolAddress((void**)&B1l, g_B1l);
    cudaGetSymbolAddress((void**)&B2h, g_B2h); cudaGetSymbolAddress((void**)&B2l, g_B2l);
    cudaGetSymbolAddress((void**)&Boh, g_Boh); cudaGetSymbolAddress((void**)&Bol, g_Bol);

    // weight prep (bf16 hi/lo planes, [N][K])
    prep_w_kernel<<<(DIN  * DHID + 255) / 256, 256>>>(W1, B1h, B1l, DIN,  DHID);
    prep_w_kernel<<<(DHID * DHID + 255) / 256, 256>>>(W2, B2h, B2l, DHID, DHID);
    prep_w_kernel<<<(DHID * DOUT + 255) / 256, 256>>>(Wo, Boh, Bol, DHID, DOUT);

    // 1) agg = x
    init_agg_kernel<<<(NN * DIN / 4 + 255) / 256, 256>>>((const float4*)x);
    // 2) agg[dst] += x[src]
    {
        long long threads = (long long)NE * 32;
        scatter_kernel<<<(int)((threads + 255) / 256), 256>>>(x, ei);
    }

    const int gx = (NN + 127) / 128;   // 782
    // 3) h1 = relu(agg @ W1 + b1)
    gin_gemm<DIN, DHID, true, false><<<dim3(gx, DHID / 128), 256>>>(
        agg, B1h, B1l, b1, h1, nullptr, NN);
    // 4) h2 = relu(h1 @ W2 + b2)
    gin_gemm<DHID, DHID, true, false><<<dim3(gx, DHID / 128), 256>>>(
        h1, B2h, B2l, b2, h2, nullptr, NN);
    // 5) pooled = segment_sum(h2 @ Wo + bo)
    cudaMemsetAsync(d_out, 0, (size_t)out_size * sizeof(float));
    gin_gemm<DHID, DOUT, false, true><<<dim3(gx, 1), 256>>>(
        h2, Boh, Bol, bo, out, bid, NN);
}

// round 6
// speedup vs baseline: 2.7260x; 1.2447x over previous
#include <cuda_runtime.h>
#include <cuda_bf16.h>
#include <cstdint>

#define NN 100000
#define NE 1600000
#define NG 512
#define DIN 128
#define DHID 256
#define DOUT 128
#define NB ((NN + 255) / 256)   // 391 scan blocks

// ---------------- scratch (device globals; allocation-free rule) -----------
__device__ float4 g_agg4[NN * DIN  / 4];   //  51.2 MB
__device__ float4 g_h1_4[NN * DHID / 4];   // 102.4 MB
__device__ float4 g_h2_4[NN * DHID / 4];   // 102.4 MB

// CSR scratch
__device__ int g_deg [NN];
__device__ int g_excl[NN];
__device__ int g_off [NN];
__device__ int g_cur [NN];
__device__ int g_bsum[512];
__device__ int g_adj [NE];

// bf16 hi/lo weight planes, layout B[n][k]  (K-major = mma ".col" operand)
__device__ __nv_bfloat16 g_B1h[DHID * DIN ], g_B1l[DHID * DIN ];
__device__ __nv_bfloat16 g_B2h[DHID * DHID], g_B2l[DHID * DHID];
__device__ __nv_bfloat16 g_Boh[DOUT * DHID], g_Bol[DOUT * DHID];

// ---------------- helpers ---------------------------------------------------
__device__ __forceinline__ uint32_t smem_u32(const void* p) {
    uint32_t a;
    asm("{ .reg .u64 t; cvta.to.shared.u64 t, %1; cvt.u32.u64 %0, t; }" : "=r"(a) : "l"(p));
    return a;
}
__device__ __forceinline__ void red_add_v2(float* p, float a, float b) {
    asm volatile("red.global.add.v2.f32 [%0], {%1,%2};"
                 :: "l"(p), "f"(a), "f"(b) : "memory");
}
#define LDSM4(r, a) \
    asm volatile("ldmatrix.sync.aligned.m8n8.x4.shared.b16 {%0,%1,%2,%3}, [%4];" \
        : "=r"((r)[0]), "=r"((r)[1]), "=r"((r)[2]), "=r"((r)[3]) : "r"(a))

__device__ __forceinline__ void mma_bf16(float* d, const uint32_t* a, const uint32_t* b) {
    asm volatile("mma.sync.aligned.m16n8k16.row.col.f32.bf16.bf16.f32 "
        "{%0,%1,%2,%3}, {%4,%5,%6,%7}, {%8,%9}, {%0,%1,%2,%3};"
        : "+f"(d[0]), "+f"(d[1]), "+f"(d[2]), "+f"(d[3])
        : "r"(a[0]), "r"(a[1]), "r"(a[2]), "r"(a[3]), "r"(b[0]), "r"(b[1]));
}

// ---------------- CSR build -------------------------------------------------
__global__ void hist_kernel(const int* __restrict__ ei) {
    int e = blockIdx.x * blockDim.x + threadIdx.x;
    if (e < NE) atomicAdd(&g_deg[ei[NE + e]], 1);
}

__global__ void scan1_kernel() {
    __shared__ int s[256];
    int i = blockIdx.x * 256 + threadIdx.x;
    int v = (i < NN) ? g_deg[i] : 0;
    s[threadIdx.x] = v;
    __syncthreads();
    #pragma unroll
    for (int d = 1; d < 256; d <<= 1) {
        int t = (threadIdx.x >= d) ? s[threadIdx.x - d] : 0;
        __syncthreads();
        s[threadIdx.x] += t;
        __syncthreads();
    }
    if (i < NN) g_excl[i] = s[threadIdx.x] - v;
    if (threadIdx.x == 255) g_bsum[blockIdx.x] = s[255];
}

__global__ void scan2_kernel() {
    __shared__ int s[512];
    int i = threadIdx.x;
    int v = (i < NB) ? g_bsum[i] : 0;
    s[i] = v;
    __syncthreads();
    #pragma unroll
    for (int d = 1; d < 512; d <<= 1) {
        int t = (i >= d) ? s[i - d] : 0;
        __syncthreads();
        s[i] += t;
        __syncthreads();
    }
    if (i < NB) g_bsum[i] = s[i] - v;   // exclusive
}

__global__ void scan3_kernel() {
    int i = blockIdx.x * 256 + threadIdx.x;
    if (i < NN) {
        int o = g_excl[i] + g_bsum[blockIdx.x];
        g_off[i] = o;
        g_cur[i] = o;
    }
}

__global__ void fill_kernel(const int* __restrict__ ei) {
    int e = blockIdx.x * blockDim.x + threadIdx.x;
    if (e >= NE) return;
    int dst = ei[NE + e];
    int pos = atomicAdd(&g_cur[dst], 1);
    g_adj[pos] = ei[e];
}

// ---------------- gather: agg[n] = x[n] + sum_{s in adj[n]} x[s] ------------
// one warp per node; lane covers feature chunk lane*4..lane*4+3
__global__ void __launch_bounds__(256)
gather_kernel(const float4* __restrict__ x4) {
    int n = (blockIdx.x * blockDim.x + threadIdx.x) >> 5;
    int lane = threadIdx.x & 31;
    if (n >= NN) return;
    float4 acc = __ldg(&x4[(size_t)n * 32 + lane]);
    int beg = g_off[n], deg = g_deg[n], end = beg + deg;
    int i = beg;
    for (; i + 4 <= end; i += 4) {
        int s0 = g_adj[i], s1 = g_adj[i+1], s2 = g_adj[i+2], s3 = g_adj[i+3];
        float4 v0 = __ldg(&x4[(size_t)s0 * 32 + lane]);
        float4 v1 = __ldg(&x4[(size_t)s1 * 32 + lane]);
        float4 v2 = __ldg(&x4[(size_t)s2 * 32 + lane]);
        float4 v3 = __ldg(&x4[(size_t)s3 * 32 + lane]);
        acc.x += v0.x + v1.x + v2.x + v3.x;
        acc.y += v0.y + v1.y + v2.y + v3.y;
        acc.z += v0.z + v1.z + v2.z + v3.z;
        acc.w += v0.w + v1.w + v2.w + v3.w;
    }
    for (; i < end; i++) {
        int s = g_adj[i];
        float4 v = __ldg(&x4[(size_t)s * 32 + lane]);
        acc.x += v.x; acc.y += v.y; acc.z += v.z; acc.w += v.w;
    }
    g_agg4[(size_t)n * 32 + lane] = acc;
}

// ---------------- weight prep: W[K][N] -> Bh/Bl [N][K] bf16 ----------------
__global__ void prep_w_kernel(const float* __restrict__ W,
                              __nv_bfloat16* __restrict__ Bh,
                              __nv_bfloat16* __restrict__ Bl, int K, int N) {
    int idx = blockIdx.x * blockDim.x + threadIdx.x;
    if (idx >= K * N) return;
    int k = idx / N, n = idx % N;
    float v = W[idx];
    __nv_bfloat16 h = __float2bfloat16(v);
    __nv_bfloat16 l = __float2bfloat16(v - __bfloat162float(h));
    Bh[(size_t)n * K + k] = h;
    Bl[(size_t)n * K + k] = l;
}

// ---------------- mma.sync GEMM: C = act(A @ W + b), optional fused pool ---
// 256 threads = 8 warps (4 x 2).  Block tile M=128, N=128, K chunk 32.
// Warp tile m32 x n64.  Split-bf16: 3 MMAs per (hi,lo) operand pair.
template<int K, int N, bool RELU, bool POOL>
__global__ void __launch_bounds__(256)
gin_gemm(const float* __restrict__ A,
         const __nv_bfloat16* __restrict__ Bh_g,
         const __nv_bfloat16* __restrict__ Bl_g,
         const float* __restrict__ bias, float* __restrict__ C,
         const int* __restrict__ batch_ids, int M)
{
    constexpr int KC    = K / 32;
    constexpr int PITCH = 80;                 // 64B data + 16B pad (conflict-free LDSM)
    constexpr int PLANE = 128 * PITCH;        // 10240 B
    constexpr int A_HI = 0, A_LO = PLANE, B_HI = 2 * PLANE, B_LO = 3 * PLANE;

    __shared__ __align__(16) char smem[4 * PLANE];   // 40 KB
    const uint32_t sb = smem_u32(smem);

    const int tid  = threadIdx.x;
    const int wid  = tid >> 5, lane = tid & 31;
    const int wm   = wid & 3, wn = wid >> 2;          // warp grid 4 x 2
    const int g    = lane >> 2, tig = lane & 3;
    const int row0 = blockIdx.x * 128;
    const int ncol0 = blockIdx.y * 128;

    const int srow = tid >> 1, shalf = tid & 1;
    const int gr_l = row0 + srow;

    uint32_t aoff[2], boff[4];
    {
        int ar = (lane & 7) + ((lane >> 3) & 1) * 8;
        int ak = ((lane >> 4) & 1) * 16;
        #pragma unroll
        for (int mi = 0; mi < 2; mi++)
            aoff[mi] = sb + A_HI + (uint32_t)((wm * 32 + mi * 16 + ar) * PITCH + ak);
        int br = (lane & 7) + ((lane >> 4) & 1) * 8;
        int bk = ((lane >> 3) & 1) * 16;
        #pragma unroll
        for (int ni2 = 0; ni2 < 4; ni2++)
            boff[ni2] = sb + B_HI + (uint32_t)((wn * 64 + ni2 * 16 + br) * PITCH + bk);
    }

    float acc[2][8][4];
    #pragma unroll
    for (int mi = 0; mi < 2; mi++)
        #pragma unroll
        for (int ni = 0; ni < 8; ni++)
            #pragma unroll
            for (int q = 0; q < 4; q++) acc[mi][ni][q] = 0.f;

    for (int kc = 0; kc < KC; kc++) {
        // ---- stage A: fp32 -> bf16 hi/lo ----
        {
            float fl[16];
            if (gr_l < M) {
                const float4* ap = reinterpret_cast<const float4*>(
                    A + (size_t)gr_l * K + kc * 32 + shalf * 16);
                #pragma unroll
                for (int j = 0; j < 4; j++) {
                    float4 v = ap[j];
                    fl[4*j] = v.x; fl[4*j+1] = v.y; fl[4*j+2] = v.z; fl[4*j+3] = v.w;
                }
            } else {
                #pragma unroll
                for (int j = 0; j < 16; j++) fl[j] = 0.f;
            }
            uint32_t hw[8], lw[8];
            #pragma unroll
            for (int i = 0; i < 8; i++) {
                float a = fl[2*i], b = fl[2*i+1];
                __nv_bfloat16 ha = __float2bfloat16(a), hb = __float2bfloat16(b);
                __nv_bfloat16 la = __float2bfloat16(a - __bfloat162float(ha));
                __nv_bfloat16 lb = __float2bfloat16(b - __bfloat162float(hb));
                __nv_bfloat162 hp = __halves2bfloat162(ha, hb);
                __nv_bfloat162 lp = __halves2bfloat162(la, lb);
                hw[i] = *reinterpret_cast<uint32_t*>(&hp);
                lw[i] = *reinterpret_cast<uint32_t*>(&lp);
            }
            char* dsthi = smem + A_HI + srow * PITCH + shalf * 32;
            char* dstlo = smem + A_LO + srow * PITCH + shalf * 32;
            *reinterpret_cast<uint4*>(dsthi)      = make_uint4(hw[0], hw[1], hw[2], hw[3]);
            *reinterpret_cast<uint4*>(dsthi + 16) = make_uint4(hw[4], hw[5], hw[6], hw[7]);
            *reinterpret_cast<uint4*>(dstlo)      = make_uint4(lw[0], lw[1], lw[2], lw[3]);
            *reinterpret_cast<uint4*>(dstlo + 16) = make_uint4(lw[4], lw[5], lw[6], lw[7]);
        }
        // ---- stage B (already bf16, plain copy) ----
        {
            int n = ncol0 + srow;
            const uint4* bh = reinterpret_cast<const uint4*>(
                Bh_g + (size_t)n * K + kc * 32 + shalf * 16);
            const uint4* bl = reinterpret_cast<const uint4*>(
                Bl_g + (size_t)n * K + kc * 32 + shalf * 16);
            char* dsthi = smem + B_HI + srow * PITCH + shalf * 32;
            char* dstlo = smem + B_LO + srow * PITCH + shalf * 32;
            *reinterpret_cast<uint4*>(dsthi)      = bh[0];
            *reinterpret_cast<uint4*>(dsthi + 16) = bh[1];
            *reinterpret_cast<uint4*>(dstlo)      = bl[0];
            *reinterpret_cast<uint4*>(dstlo + 16) = bl[1];
        }
        __syncthreads();

        #pragma unroll
        for (int kk = 0; kk < 2; kk++) {
            uint32_t ah[2][4], al[2][4];
            #pragma unroll
            for (int mi = 0; mi < 2; mi++) {
                LDSM4(ah[mi], aoff[mi] + kk * 32);
                LDSM4(al[mi], aoff[mi] + kk * 32 + PLANE);
            }
            #pragma unroll
            for (int ni2 = 0; ni2 < 4; ni2++) {
                uint32_t bh[4], bl[4];
                LDSM4(bh, boff[ni2] + kk * 32);
                LDSM4(bl, boff[ni2] + kk * 32 + PLANE);
                #pragma unroll
                for (int mi = 0; mi < 2; mi++) {
                    mma_bf16(acc[mi][2*ni2],   ah[mi], bh);
                    mma_bf16(acc[mi][2*ni2],   ah[mi], bl);
                    mma_bf16(acc[mi][2*ni2],   al[mi], bh);
                    mma_bf16(acc[mi][2*ni2+1], ah[mi], bh + 2);
                    mma_bf16(acc[mi][2*ni2+1], ah[mi], bl + 2);
                    mma_bf16(acc[mi][2*ni2+1], al[mi], bh + 2);
                }
            }
        }
        __syncthreads();
    }

    // ---- epilogue ----
    if (!POOL) {
        #pragma unroll
        for (int mi = 0; mi < 2; mi++) {
            int r0 = row0 + wm * 32 + mi * 16 + g;
            #pragma unroll
            for (int ni = 0; ni < 8; ni++) {
                int cg = ncol0 + wn * 64 + ni * 8 + tig * 2;
                float bx = bias[cg], by = bias[cg + 1];
                if (r0 < M) {
                    float2 o;
                    o.x = acc[mi][ni][0] + bx;
                    o.y = acc[mi][ni][1] + by;
                    if (RELU) { o.x = fmaxf(o.x, 0.f); o.y = fmaxf(o.y, 0.f); }
                    *reinterpret_cast<float2*>(&C[(size_t)r0 * N + cg]) = o;
                }
                if (r0 + 8 < M) {
                    float2 o;
                    o.x = acc[mi][ni][2] + bx;
                    o.y = acc[mi][ni][3] + by;
                    if (RELU) { o.x = fmaxf(o.x, 0.f); o.y = fmaxf(o.y, 0.f); }
                    *reinterpret_cast<float2*>(&C[(size_t)(r0 + 8) * N + cg]) = o;
                }
            }
        }
    } else {
        int base = row0 + wm * 32 + g;
        int rows[4] = { base, base + 8, base + 16, base + 24 };
        int bids[4];
        #pragma unroll
        for (int e = 0; e < 4; e++)
            bids[e] = (rows[e] < M) ? batch_ids[rows[e]] : -1;

        #pragma unroll
        for (int ni = 0; ni < 8; ni++) {
            int cg = ncol0 + wn * 64 + ni * 8 + tig * 2;
            float bx = bias[cg], by = bias[cg + 1];
            float v0[4], v1[4];
            v0[0] = acc[0][ni][0] + bx; v1[0] = acc[0][ni][1] + by;
            v0[1] = acc[0][ni][2] + bx; v1[1] = acc[0][ni][3] + by;
            v0[2] = acc[1][ni][0] + bx; v1[2] = acc[1][ni][1] + by;
            v0[3] = acc[1][ni][2] + bx; v1[3] = acc[1][ni][3] + by;
            int cur = -1; float s0 = 0.f, s1 = 0.f;
            #pragma unroll
            for (int e = 0; e < 4; e++) {
                if (bids[e] < 0) continue;
                if (bids[e] != cur) {
                    if (cur >= 0) red_add_v2(&C[(size_t)cur * N + cg], s0, s1);
                    cur = bids[e]; s0 = 0.f; s1 = 0.f;
                }
                s0 += v0[e]; s1 += v1[e];
            }
            if (cur >= 0) red_add_v2(&C[(size_t)cur * N + cg], s0, s1);
        }
    }
}

// ---------------- launch ---------------------------------------------------
extern "C" void kernel_launch(void* const* d_in, const int* in_sizes, int n_in,
                              void* d_out, int out_size)
{
    const float* x   = (const float*)d_in[0];
    const int*   ei  = (const int*)d_in[1];
    const int*   bid = (const int*)d_in[2];
    const float* W1  = (const float*)d_in[3];
    const float* b1  = (const float*)d_in[4];
    const float* W2  = (const float*)d_in[5];
    const float* b2  = (const float*)d_in[6];
    const float* Wo  = (const float*)d_in[7];
    const float* bo  = (const float*)d_in[8];
    float*       out = (float*)d_out;

    float *agg, *h1, *h2;
    cudaGetSymbolAddress((void**)&agg, g_agg4);
    cudaGetSymbolAddress((void**)&h1,  g_h1_4);
    cudaGetSymbolAddress((void**)&h2,  g_h2_4);
    __nv_bfloat16 *B1h, *B1l, *B2h, *B2l, *Boh, *Bol;
    cudaGetSymbolAddress((void**)&B1h, g_B1h); cudaGetSymbolAddress((void**)&B1l, g_B1l);
    cudaGetSymbolAddress((void**)&B2h, g_B2h); cudaGetSymbolAddress((void**)&B2l, g_B2l);
    cudaGetSymbolAddress((void**)&Boh, g_Boh); cudaGetSymbolAddress((void**)&Bol, g_Bol);
    int* deg; cudaGetSymbolAddress((void**)&deg, g_deg);

    // weight prep (bf16 hi/lo planes, [N][K])
    prep_w_kernel<<<(DIN  * DHID + 255) / 256, 256>>>(W1, B1h, B1l, DIN,  DHID);
    prep_w_kernel<<<(DHID * DHID + 255) / 256, 256>>>(W2, B2h, B2l, DHID, DHID);
    prep_w_kernel<<<(DHID * DOUT + 255) / 256, 256>>>(Wo, Boh, Bol, DHID, DOUT);

    // ---- CSR build (re-done every launch; deg must be zeroed) ----
    cudaMemsetAsync(deg, 0, NN * sizeof(int));
    hist_kernel<<<(NE + 255) / 256, 256>>>(ei);
    scan1_kernel<<<NB, 256>>>();
    scan2_kernel<<<1, 512>>>();
    scan3_kernel<<<NB, 256>>>();
    fill_kernel<<<(NE + 255) / 256, 256>>>(ei);

    // ---- gather: agg = x + neighbor sum (warp per node) ----
    gather_kernel<<<(NN * 32 + 255) / 256, 256>>>((const float4*)x);

    const int gx = (NN + 127) / 128;   // 782
    // h1 = relu(agg @ W1 + b1)
    gin_gemm<DIN, DHID, true, false><<<dim3(gx, DHID / 128), 256>>>(
        agg, B1h, B1l, b1, h1, nullptr, NN);
    // h2 = relu(h1 @ W2 + b2)
    gin_gemm<DHID, DHID, true, false><<<dim3(gx, DHID / 128), 256>>>(
        h1, B2h, B2l, b2, h2, nullptr, NN);
    // pooled = segment_sum(h2 @ Wo + bo)
    cudaMemsetAsync(d_out, 0, (size_t)out_size * sizeof(float));
    gin_gemm<DHID, DOUT, false, true><<<dim3(gx, 1), 256>>>(
        h2, Boh, Bol, bo, out, bid, NN);
}

// round 7
// speedup vs baseline: 3.2514x; 1.1927x over previous
#include <cuda_runtime.h>
#include <cuda_bf16.h>
#include <cstdint>

#define NN 100000
#define NE 1600000
#define NG 512
#define DIN 128
#define DHID 256
#define DOUT 128
#define NB ((NN + 255) / 256)   // 391 scan blocks

// ---------------- scratch (device globals; allocation-free rule) -----------
// activations as pre-split bf16 hi/lo planes
__device__ __nv_bfloat16 g_aggH[NN * DIN ], g_aggL[NN * DIN ];   // 25.6 MB x2
__device__ __nv_bfloat16 g_h1H [NN * DHID], g_h1L [NN * DHID];   // 51.2 MB x2
__device__ __nv_bfloat16 g_h2H [NN * DHID], g_h2L [NN * DHID];   // 51.2 MB x2

// CSR scratch
__device__ int g_deg [NN];
__device__ int g_excl[NN];
__device__ int g_off [NN];
__device__ int g_cur [NN];
__device__ int g_bsum[512];
__device__ int g_adj [NE];

// bf16 hi/lo weight planes, layout B[n][k]  (K-major = mma ".col" operand)
__device__ __nv_bfloat16 g_B1h[DHID * DIN ], g_B1l[DHID * DIN ];
__device__ __nv_bfloat16 g_B2h[DHID * DHID], g_B2l[DHID * DHID];
__device__ __nv_bfloat16 g_Boh[DOUT * DHID], g_Bol[DOUT * DHID];

// ---------------- helpers ---------------------------------------------------
__device__ __forceinline__ uint32_t smem_u32(const void* p) {
    uint32_t a;
    asm("{ .reg .u64 t; cvta.to.shared.u64 t, %1; cvt.u32.u64 %0, t; }" : "=r"(a) : "l"(p));
    return a;
}
__device__ __forceinline__ void red_add_v2(float* p, float a, float b) {
    asm volatile("red.global.add.v2.f32 [%0], {%1,%2};"
                 :: "l"(p), "f"(a), "f"(b) : "memory");
}
__device__ __forceinline__ void cpa16(uint32_t dst, const void* src, int sz) {
    asm volatile("cp.async.ca.shared.global [%0], [%1], 16, %2;"
                 :: "r"(dst), "l"(src), "r"(sz) : "memory");
}
#define CP_COMMIT()  asm volatile("cp.async.commit_group;" ::: "memory")
#define CP_WAIT(n)   asm volatile("cp.async.wait_group %0;" :: "n"(n) : "memory")

#define LDSM4(r, a) \
    asm volatile("ldmatrix.sync.aligned.m8n8.x4.shared.b16 {%0,%1,%2,%3}, [%4];" \
        : "=r"((r)[0]), "=r"((r)[1]), "=r"((r)[2]), "=r"((r)[3]) : "r"(a))

__device__ __forceinline__ void mma_bf16(float* d, const uint32_t* a, const uint32_t* b) {
    asm volatile("mma.sync.aligned.m16n8k16.row.col.f32.bf16.bf16.f32 "
        "{%0,%1,%2,%3}, {%4,%5,%6,%7}, {%8,%9}, {%0,%1,%2,%3};"
        : "+f"(d[0]), "+f"(d[1]), "+f"(d[2]), "+f"(d[3])
        : "r"(a[0]), "r"(a[1]), "r"(a[2]), "r"(a[3]), "r"(b[0]), "r"(b[1]));
}

__device__ __forceinline__ uint32_t pack_hi(float a, float b) {
    __nv_bfloat162 p = __halves2bfloat162(__float2bfloat16(a), __float2bfloat16(b));
    return *reinterpret_cast<uint32_t*>(&p);
}
__device__ __forceinline__ uint32_t pack_lo(float a, float b) {
    __nv_bfloat16 ha = __float2bfloat16(a), hb = __float2bfloat16(b);
    __nv_bfloat162 p = __halves2bfloat162(
        __float2bfloat16(a - __bfloat162float(ha)),
        __float2bfloat16(b - __bfloat162float(hb)));
    return *reinterpret_cast<uint32_t*>(&p);
}

// ---------------- CSR build -------------------------------------------------
__global__ void hist_kernel(const int* __restrict__ ei) {
    int e = blockIdx.x * blockDim.x + threadIdx.x;
    if (e < NE) atomicAdd(&g_deg[ei[NE + e]], 1);
}

__global__ void scan1_kernel() {
    __shared__ int s[256];
    int i = blockIdx.x * 256 + threadIdx.x;
    int v = (i < NN) ? g_deg[i] : 0;
    s[threadIdx.x] = v;
    __syncthreads();
    #pragma unroll
    for (int d = 1; d < 256; d <<= 1) {
        int t = (threadIdx.x >= d) ? s[threadIdx.x - d] : 0;
        __syncthreads();
        s[threadIdx.x] += t;
        __syncthreads();
    }
    if (i < NN) g_excl[i] = s[threadIdx.x] - v;
    if (threadIdx.x == 255) g_bsum[blockIdx.x] = s[255];
}

__global__ void scan2_kernel() {
    __shared__ int s[512];
    int i = threadIdx.x;
    int v = (i < NB) ? g_bsum[i] : 0;
    s[i] = v;
    __syncthreads();
    #pragma unroll
    for (int d = 1; d < 512; d <<= 1) {
        int t = (i >= d) ? s[i - d] : 0;
        __syncthreads();
        s[i] += t;
        __syncthreads();
    }
    if (i < NB) g_bsum[i] = s[i] - v;   // exclusive
}

__global__ void scan3_kernel() {
    int i = blockIdx.x * 256 + threadIdx.x;
    if (i < NN) {
        int o = g_excl[i] + g_bsum[blockIdx.x];
        g_off[i] = o;
        g_cur[i] = o;
    }
}

__global__ void fill_kernel(const int* __restrict__ ei) {
    int e = blockIdx.x * blockDim.x + threadIdx.x;
    if (e >= NE) return;
    int dst = ei[NE + e];
    int pos = atomicAdd(&g_cur[dst], 1);
    g_adj[pos] = ei[e];
}

// ---------------- gather: agg[n] = x[n] + sum_{s in adj[n]} x[s] ------------
// one warp per node; lane covers feature chunk lane*4..lane*4+3
// output: bf16 hi/lo planes
__global__ void __launch_bounds__(256)
gather_kernel(const float4* __restrict__ x4) {
    int n = (blockIdx.x * blockDim.x + threadIdx.x) >> 5;
    int lane = threadIdx.x & 31;
    if (n >= NN) return;
    float4 acc = __ldg(&x4[(size_t)n * 32 + lane]);
    int beg = g_off[n], deg = g_deg[n], end = beg + deg;
    int i = beg;
    for (; i + 4 <= end; i += 4) {
        int s0 = g_adj[i], s1 = g_adj[i+1], s2 = g_adj[i+2], s3 = g_adj[i+3];
        float4 v0 = __ldg(&x4[(size_t)s0 * 32 + lane]);
        float4 v1 = __ldg(&x4[(size_t)s1 * 32 + lane]);
        float4 v2 = __ldg(&x4[(size_t)s2 * 32 + lane]);
        float4 v3 = __ldg(&x4[(size_t)s3 * 32 + lane]);
        acc.x += v0.x + v1.x + v2.x + v3.x;
        acc.y += v0.y + v1.y + v2.y + v3.y;
        acc.z += v0.z + v1.z + v2.z + v3.z;
        acc.w += v0.w + v1.w + v2.w + v3.w;
    }
    for (; i < end; i++) {
        int s = g_adj[i];
        float4 v = __ldg(&x4[(size_t)s * 32 + lane]);
        acc.x += v.x; acc.y += v.y; acc.z += v.z; acc.w += v.w;
    }
    uint2 h = make_uint2(pack_hi(acc.x, acc.y), pack_hi(acc.z, acc.w));
    uint2 l = make_uint2(pack_lo(acc.x, acc.y), pack_lo(acc.z, acc.w));
    *reinterpret_cast<uint2*>(g_aggH + (size_t)n * DIN + lane * 4) = h;
    *reinterpret_cast<uint2*>(g_aggL + (size_t)n * DIN + lane * 4) = l;
}

// ---------------- weight prep: W[K][N] -> Bh/Bl [N][K] bf16 ----------------
__global__ void prep_w_kernel(const float* __restrict__ W,
                              __nv_bfloat16* __restrict__ Bh,
                              __nv_bfloat16* __restrict__ Bl, int K, int N) {
    int idx = blockIdx.x * blockDim.x + threadIdx.x;
    if (idx >= K * N) return;
    int k = idx / N, n = idx % N;
    float v = W[idx];
    __nv_bfloat16 h = __float2bfloat16(v);
    __nv_bfloat16 l = __float2bfloat16(v - __bfloat162float(h));
    Bh[(size_t)n * K + k] = h;
    Bl[(size_t)n * K + k] = l;
}

// ---------------- mma.sync GEMM, cp.async 2-stage pipeline -----------------
// 256 threads = 8 warps (4 x 2).  Block tile M=128, N=128, K chunk 32.
// Warp tile m32 x n64.  Split-bf16: 3 MMAs per (hi,lo) operand pair.
// A,B inputs pre-split bf16 hi/lo.  Output: bf16 hi/lo planes, or fused pool.
template<int K, int N, bool RELU, bool POOL>
__global__ void __launch_bounds__(256)
gin_gemm(const __nv_bfloat16* __restrict__ Ah_g,
         const __nv_bfloat16* __restrict__ Al_g,
         const __nv_bfloat16* __restrict__ Bh_g,
         const __nv_bfloat16* __restrict__ Bl_g,
         const float* __restrict__ bias,
         __nv_bfloat16* __restrict__ Ch, __nv_bfloat16* __restrict__ Cl,
         float* __restrict__ Cp, const int* __restrict__ batch_ids, int M)
{
    constexpr int KC    = K / 32;
    constexpr int PITCH = 80;                 // 64B data + 16B pad (conflict-free LDSM)
    constexpr int PLANE = 128 * PITCH;        // 10240 B
    constexpr int STAGE = 4 * PLANE;          // 40960 B

    extern __shared__ __align__(16) char smem[];
    const uint32_t sb = smem_u32(smem);

    const int tid  = threadIdx.x;
    const int wid  = tid >> 5, lane = tid & 31;
    const int wm   = wid & 3, wn = wid >> 2;
    const int g    = lane >> 2, tig = lane & 3;
    const int row0 = blockIdx.x * 128;
    const int ncol0 = blockIdx.y * 128;

    // cp.async staging roles: thread t -> row (t>>2) & (t>>2)+64, seg t&3
    const int rlo = tid >> 2, seg = tid & 3;

    auto issue = [&](int s, int kc) {
        const int kof = kc * 32 + seg * 8;
        const uint32_t sbase = sb + s * STAGE;
        #pragma unroll
        for (int half = 0; half < 2; half++) {
            int row = half * 64 + rlo;
            int gr = row0 + row;
            int sz = (gr < M) ? 16 : 0;
            int grc = (gr < M) ? gr : 0;
            uint32_t doff = (uint32_t)(row * PITCH + seg * 16);
            cpa16(sbase + 0 * PLANE + doff, Ah_g + (size_t)grc * K + kof, sz);
            cpa16(sbase + 1 * PLANE + doff, Al_g + (size_t)grc * K + kof, sz);
            int bn = ncol0 + row;
            cpa16(sbase + 2 * PLANE + doff, Bh_g + (size_t)bn * K + kof, 16);
            cpa16(sbase + 3 * PLANE + doff, Bl_g + (size_t)bn * K + kof, 16);
        }
        CP_COMMIT();
    };

    // ldmatrix lane base offsets (stage 0, hi planes, kk=0)
    uint32_t aoff[2], boff[4];
    {
        int ar = (lane & 7) + ((lane >> 3) & 1) * 8;
        int ak = ((lane >> 4) & 1) * 16;
        #pragma unroll
        for (int mi = 0; mi < 2; mi++)
            aoff[mi] = sb + (uint32_t)((wm * 32 + mi * 16 + ar) * PITCH + ak);
        int br = (lane & 7) + ((lane >> 4) & 1) * 8;
        int bk = ((lane >> 3) & 1) * 16;
        #pragma unroll
        for (int ni2 = 0; ni2 < 4; ni2++)
            boff[ni2] = sb + 2 * PLANE + (uint32_t)((wn * 64 + ni2 * 16 + br) * PITCH + bk);
    }

    float acc[2][8][4];
    #pragma unroll
    for (int mi = 0; mi < 2; mi++)
        #pragma unroll
        for (int ni = 0; ni < 8; ni++)
            #pragma unroll
            for (int q = 0; q < 4; q++) acc[mi][ni][q] = 0.f;

    issue(0, 0);

    for (int kc = 0; kc < KC; kc++) {
        if (kc + 1 < KC) { issue((kc + 1) & 1, kc + 1); CP_WAIT(1); }
        else             { CP_WAIT(0); }
        __syncthreads();

        const uint32_t so = (uint32_t)((kc & 1) * STAGE);
        #pragma unroll
        for (int kk = 0; kk < 2; kk++) {
            uint32_t ah[2][4], al[2][4];
            #pragma unroll
            for (int mi = 0; mi < 2; mi++) {
                LDSM4(ah[mi], aoff[mi] + so + kk * 32);
                LDSM4(al[mi], aoff[mi] + so + kk * 32 + PLANE);
            }
            #pragma unroll
            for (int ni2 = 0; ni2 < 4; ni2++) {
                uint32_t bh[4], bl[4];
                LDSM4(bh, boff[ni2] + so + kk * 32);
                LDSM4(bl, boff[ni2] + so + kk * 32 + PLANE);
                #pragma unroll
                for (int mi = 0; mi < 2; mi++) {
                    mma_bf16(acc[mi][2*ni2],   ah[mi], bh);
                    mma_bf16(acc[mi][2*ni2],   ah[mi], bl);
                    mma_bf16(acc[mi][2*ni2],   al[mi], bh);
                    mma_bf16(acc[mi][2*ni2+1], ah[mi], bh + 2);
                    mma_bf16(acc[mi][2*ni2+1], ah[mi], bl + 2);
                    mma_bf16(acc[mi][2*ni2+1], al[mi], bh + 2);
                }
            }
        }
        __syncthreads();
    }

    // ---- epilogue ----
    if (!POOL) {
        #pragma unroll
        for (int mi = 0; mi < 2; mi++) {
            int r0 = row0 + wm * 32 + mi * 16 + g;
            #pragma unroll
            for (int ni = 0; ni < 8; ni++) {
                int cg = ncol0 + wn * 64 + ni * 8 + tig * 2;
                float bx = bias[cg], by = bias[cg + 1];
                if (r0 < M) {
                    float ox = acc[mi][ni][0] + bx, oy = acc[mi][ni][1] + by;
                    if (RELU) { ox = fmaxf(ox, 0.f); oy = fmaxf(oy, 0.f); }
                    *reinterpret_cast<uint32_t*>(Ch + (size_t)r0 * N + cg) = pack_hi(ox, oy);
                    *reinterpret_cast<uint32_t*>(Cl + (size_t)r0 * N + cg) = pack_lo(ox, oy);
                }
                if (r0 + 8 < M) {
                    float ox = acc[mi][ni][2] + bx, oy = acc[mi][ni][3] + by;
                    if (RELU) { ox = fmaxf(ox, 0.f); oy = fmaxf(oy, 0.f); }
                    *reinterpret_cast<uint32_t*>(Ch + (size_t)(r0+8) * N + cg) = pack_hi(ox, oy);
                    *reinterpret_cast<uint32_t*>(Cl + (size_t)(r0+8) * N + cg) = pack_lo(ox, oy);
                }
            }
        }
    } else {
        int base = row0 + wm * 32 + g;
        int rows[4] = { base, base + 8, base + 16, base + 24 };
        int bids[4];
        #pragma unroll
        for (int e = 0; e < 4; e++)
            bids[e] = (rows[e] < M) ? batch_ids[rows[e]] : -1;

        #pragma unroll
        for (int ni = 0; ni < 8; ni++) {
            int cg = ncol0 + wn * 64 + ni * 8 + tig * 2;
            float bx = bias[cg], by = bias[cg + 1];
            float v0[4], v1[4];
            v0[0] = acc[0][ni][0] + bx; v1[0] = acc[0][ni][1] + by;
            v0[1] = acc[0][ni][2] + bx; v1[1] = acc[0][ni][3] + by;
            v0[2] = acc[1][ni][0] + bx; v1[2] = acc[1][ni][1] + by;
            v0[3] = acc[1][ni][2] + bx; v1[3] = acc[1][ni][3] + by;
            int cur = -1; float s0 = 0.f, s1 = 0.f;
            #pragma unroll
            for (int e = 0; e < 4; e++) {
                if (bids[e] < 0) continue;
                if (bids[e] != cur) {
                    if (cur >= 0) red_add_v2(&Cp[(size_t)cur * N + cg], s0, s1);
                    cur = bids[e]; s0 = 0.f; s1 = 0.f;
                }
                s0 += v0[e]; s1 += v1[e];
            }
            if (cur >= 0) red_add_v2(&Cp[(size_t)cur * N + cg], s0, s1);
        }
    }
}

// ---------------- launch ---------------------------------------------------
extern "C" void kernel_launch(void* const* d_in, const int* in_sizes, int n_in,
                              void* d_out, int out_size)
{
    const float* x   = (const float*)d_in[0];
    const int*   ei  = (const int*)d_in[1];
    const int*   bid = (const int*)d_in[2];
    const float* W1  = (const float*)d_in[3];
    const float* b1  = (const float*)d_in[4];
    const float* W2  = (const float*)d_in[5];
    const float* b2  = (const float*)d_in[6];
    const float* Wo  = (const float*)d_in[7];
    const float* bo  = (const float*)d_in[8];
    float*       out = (float*)d_out;

    __nv_bfloat16 *aggH, *aggL, *h1H, *h1L, *h2H, *h2L;
    cudaGetSymbolAddress((void**)&aggH, g_aggH); cudaGetSymbolAddress((void**)&aggL, g_aggL);
    cudaGetSymbolAddress((void**)&h1H,  g_h1H);  cudaGetSymbolAddress((void**)&h1L,  g_h1L);
    cudaGetSymbolAddress((void**)&h2H,  g_h2H);  cudaGetSymbolAddress((void**)&h2L,  g_h2L);
    __nv_bfloat16 *B1h, *B1l, *B2h, *B2l, *Boh, *Bol;
    cudaGetSymbolAddress((void**)&B1h, g_B1h); cudaGetSymbolAddress((void**)&B1l, g_B1l);
    cudaGetSymbolAddress((void**)&B2h, g_B2h); cudaGetSymbolAddress((void**)&B2l, g_B2l);
    cudaGetSymbolAddress((void**)&Boh, g_Boh); cudaGetSymbolAddress((void**)&Bol, g_Bol);
    int* deg; cudaGetSymbolAddress((void**)&deg, g_deg);

    constexpr int SMEM = 2 * 4 * 128 * 80;   // 81920 B
    cudaFuncSetAttribute(gin_gemm<DIN,  DHID, true,  false>,
                         cudaFuncAttributeMaxDynamicSharedMemorySize, SMEM);
    cudaFuncSetAttribute(gin_gemm<DHID, DHID, true,  false>,
                         cudaFuncAttributeMaxDynamicSharedMemorySize, SMEM);
    cudaFuncSetAttribute(gin_gemm<DHID, DOUT, false, true>,
                         cudaFuncAttributeMaxDynamicSharedMemorySize, SMEM);

    // weight prep (bf16 hi/lo planes, [N][K])
    prep_w_kernel<<<(DIN  * DHID + 255) / 256, 256>>>(W1, B1h, B1l, DIN,  DHID);
    prep_w_kernel<<<(DHID * DHID + 255) / 256, 256>>>(W2, B2h, B2l, DHID, DHID);
    prep_w_kernel<<<(DHID * DOUT + 255) / 256, 256>>>(Wo, Boh, Bol, DHID, DOUT);

    // ---- CSR build ----
    cudaMemsetAsync(deg, 0, NN * sizeof(int));
    hist_kernel<<<(NE + 255) / 256, 256>>>(ei);
    scan1_kernel<<<NB, 256>>>();
    scan2_kernel<<<1, 512>>>();
    scan3_kernel<<<NB, 256>>>();
    fill_kernel<<<(NE + 255) / 256, 256>>>(ei);

    // ---- gather: agg = x + neighbor sum -> bf16 hi/lo ----
    gather_kernel<<<(NN * 32 + 255) / 256, 256>>>((const float4*)x);

    const int gx = (NN + 127) / 128;   // 782
    // h1 = relu(agg @ W1 + b1)
    gin_gemm<DIN, DHID, true, false><<<dim3(gx, DHID / 128), 256, SMEM>>>(
        aggH, aggL, B1h, B1l, b1, h1H, h1L, nullptr, nullptr, NN);
    // h2 = relu(h1 @ W2 + b2)
    gin_gemm<DHID, DHID, true, false><<<dim3(gx, DHID / 128), 256, SMEM>>>(
        h1H, h1L, B2h, B2l, b2, h2H, h2L, nullptr, nullptr, NN);
    // pooled = segment_sum(h2 @ Wo + bo)
    cudaMemsetAsync(d_out, 0, (size_t)out_size * sizeof(float));
    gin_gemm<DHID, DOUT, false, true><<<dim3(gx, 1), 256, SMEM>>>(
        h2H, h2L, Boh, Bol, bo, nullptr, nullptr, out, bid, NN);
}